// round 12
// baseline (speedup 1.0000x reference)
#include <cuda_runtime.h>
#include <cuda_bf16.h>
#include <cstdint>

// Problem dims (fixed): B=64, T=1024, I=H=256, G=4H=1024
// ---------------- device scratch (static; no runtime allocations) ----------------
__device__ float         g_Wq[1024 * 256];              // quantized w_ih (fp32, exact grid values)
__device__ __nv_bfloat16 g_Whh[1024 * 256];             // quantized w_hh (exact in bf16)
__device__ float         g_bias[1024];                  // fq(b_ih)+fq(b_hh)
__device__ float         g_xs[(size_t)65536 * 1024];    // [t*64+b][g] input projections (+bias)

// ---------------- helpers ----------------
__device__ __forceinline__ float fq(float x) {
    float q = __fmul_rn(rintf(__fmul_rn(x, 16.0f)), 0.0625f);
    return fminf(fmaxf(q, -8.0f), 7.9375f);
}

// XLA EmitTanh: Cephes rational, FMA-contracted Horner, clamp 7.99881172180175781.
__device__ __forceinline__ float tanh_ref(float x) {
    float ax = fabsf(x);
    float xc = fminf(fmaxf(x, -7.99881172180175781f), 7.99881172180175781f);
    float x2 = __fmul_rn(xc, xc);
    float p = -2.76076847742355e-16f;
    p = __fmaf_rn(x2, p, 2.00018790482477e-13f);
    p = __fmaf_rn(x2, p, -8.60467152213735e-11f);
    p = __fmaf_rn(x2, p, 5.12229709037114e-08f);
    p = __fmaf_rn(x2, p, 1.48572235717979e-05f);
    p = __fmaf_rn(x2, p, 6.37261928875436e-04f);
    p = __fmaf_rn(x2, p, 4.89352455891786e-03f);
    float num = __fmul_rn(xc, p);
    float den = 1.19825839466702e-06f;
    den = __fmaf_rn(x2, den, 1.18534705686654e-04f);
    den = __fmaf_rn(x2, den, 2.26843463243900e-03f);
    den = __fmaf_rn(x2, den, 4.89352518554385e-03f);
    float r = __fdiv_rn(num, den);
    return (ax < 0.0004f) ? x : r;
}

// Faithfully-rounded expf (Juffa); immune to --use_fast_math.
__device__ __forceinline__ float expf_acc(float a) {
    float f, r, j, s, t;
    int i, ia;
    j = __fmaf_rn(1.442695f, a, 12582912.f);
    j = __fadd_rn(j, -12582912.f);
    f = __fmaf_rn(j, -6.93145752e-1f, a);
    f = __fmaf_rn(j, -1.42860677e-6f, f);
    i = (int)j;
    r = 1.37805939e-3f;
    r = __fmaf_rn(r, f, 8.37312452e-3f);
    r = __fmaf_rn(r, f, 4.16695364e-2f);
    r = __fmaf_rn(r, f, 1.66664720e-1f);
    r = __fmaf_rn(r, f, 4.99999851e-1f);
    r = __fmaf_rn(r, f, 1.00000000e+0f);
    r = __fmaf_rn(r, f, 1.00000000e+0f);
    ia = (i > 0) ? 0 : 0x83000000;
    s = __int_as_float(0x7f000000 + ia);
    t = __int_as_float((i << 23) - ia);
    r = __fmul_rn(__fmul_rn(r, s), t);
    if (fabsf(a) >= 104.0f) r = __fmul_rn(s, s);
    return r;
}

// XLA LogisticExpander: logistic(x) = 1 / (1 + exp(-x)), IEEE division.
__device__ __forceinline__ float sigmoid_ref(float x) {
    float e = expf_acc(-x);
    return __fdiv_rn(1.0f, __fadd_rn(1.0f, e));
}

__device__ __forceinline__ void mma16816(float c[4], const uint32_t a[4], const uint32_t b[2]) {
    asm volatile(
        "mma.sync.aligned.m16n8k16.row.col.f32.bf16.bf16.f32 "
        "{%0,%1,%2,%3}, {%4,%5,%6,%7}, {%8,%9}, {%0,%1,%2,%3};\n"
        : "+f"(c[0]), "+f"(c[1]), "+f"(c[2]), "+f"(c[3])
        : "r"(a[0]), "r"(a[1]), "r"(a[2]), "r"(a[3]), "r"(b[0]), "r"(b[1]));
}

// ---------------- prep kernel ----------------
__global__ void k_prep_w(const float* __restrict__ wih, const float* __restrict__ whh,
                         const float* __restrict__ bih, const float* __restrict__ bhh) {
    int g = blockIdx.x;          // 0..1023
    int k = threadIdx.x;         // 0..255
    g_Wq[g * 256 + k] = fq(wih[g * 256 + k]);
    g_Whh[g * 256 + k] = __float2bfloat16(fq(whh[g * 256 + k]));   // exact (j/16, |j|<=128)
    if (k == 0) g_bias[g] = __fadd_rn(fq(bih[g]), fq(bhh[g]));
}

// ---------------- input projection: exact sequential-chain SGEMM ----------------
// Same FMA chain order per element as R11 (bitwise identical); loads vectorized to LDS.128.
__global__ void __launch_bounds__(256) k_gemm_chain(const float* __restrict__ x) {
    __shared__ float Xs[32][132];   // [k][m], plain
    __shared__ float Ws[32][132];   // [k][g], plain
    const int tid = threadIdx.x;
    const int m0 = blockIdx.y * 128, n0 = blockIdx.x * 128;
    const int tm = tid >> 4;
    const int tn = tid & 15;

    float bias0[8];
#pragma unroll
    for (int j = 0; j < 8; j++) bias0[j] = g_bias[n0 + tn * 8 + j];

    unsigned long long acc[8][4];
#pragma unroll
    for (int i = 0; i < 8; i++)
#pragma unroll
        for (int j = 0; j < 4; j++) acc[i][j] = 0ull;

    for (int kc = 0; kc < 256; kc += 32) {
        __syncthreads();
#pragma unroll
        for (int j = 0; j < 4; j++) {
            int f4 = tid + 256 * j;
            int mr = f4 >> 3;
            int kq = (f4 & 7) * 4;
            float4 xv = *(const float4*)(x + (size_t)(m0 + mr) * 256 + kc + kq);
            Xs[kq + 0][mr] = xv.x;
            Xs[kq + 1][mr] = xv.y;
            Xs[kq + 2][mr] = xv.z;
            Xs[kq + 3][mr] = xv.w;
            float4 wv = *(const float4*)(g_Wq + (size_t)(n0 + mr) * 256 + kc + kq);
            Ws[kq + 0][mr] = wv.x;
            Ws[kq + 1][mr] = wv.y;
            Ws[kq + 2][mr] = wv.z;
            Ws[kq + 3][mr] = wv.w;
        }
        __syncthreads();
#pragma unroll 4
        for (int k = 0; k < 32; k++) {
            float4 xa = *(const float4*)&Xs[k][tm * 8];
            float4 xb = *(const float4*)&Xs[k][tm * 8 + 4];
            float4 wa = *(const float4*)&Ws[k][tn * 8];
            float4 wb = *(const float4*)&Ws[k][tn * 8 + 4];
            unsigned long long a2[8];
            asm("mov.b64 %0, {%1, %1};" : "=l"(a2[0]) : "f"(xa.x));
            asm("mov.b64 %0, {%1, %1};" : "=l"(a2[1]) : "f"(xa.y));
            asm("mov.b64 %0, {%1, %1};" : "=l"(a2[2]) : "f"(xa.z));
            asm("mov.b64 %0, {%1, %1};" : "=l"(a2[3]) : "f"(xa.w));
            asm("mov.b64 %0, {%1, %1};" : "=l"(a2[4]) : "f"(xb.x));
            asm("mov.b64 %0, {%1, %1};" : "=l"(a2[5]) : "f"(xb.y));
            asm("mov.b64 %0, {%1, %1};" : "=l"(a2[6]) : "f"(xb.z));
            asm("mov.b64 %0, {%1, %1};" : "=l"(a2[7]) : "f"(xb.w));
            unsigned long long b2[4];
            asm("mov.b64 %0, {%1, %2};" : "=l"(b2[0]) : "f"(wa.x), "f"(wa.y));
            asm("mov.b64 %0, {%1, %2};" : "=l"(b2[1]) : "f"(wa.z), "f"(wa.w));
            asm("mov.b64 %0, {%1, %2};" : "=l"(b2[2]) : "f"(wb.x), "f"(wb.y));
            asm("mov.b64 %0, {%1, %2};" : "=l"(b2[3]) : "f"(wb.z), "f"(wb.w));
#pragma unroll
            for (int i = 0; i < 8; i++)
#pragma unroll
                for (int jp = 0; jp < 4; jp++)
                    asm("fma.rn.f32x2 %0, %1, %2, %0;" : "+l"(acc[i][jp]) : "l"(a2[i]), "l"(b2[jp]));
        }
    }

#pragma unroll
    for (int i = 0; i < 8; i++) {
        int m = m0 + tm * 8 + i;
        int row = (m & 1023) * 64 + (m >> 10);
        float v[8];
#pragma unroll
        for (int jp = 0; jp < 4; jp++) {
            float lo, hi;
            asm("mov.b64 {%0, %1}, %2;" : "=f"(lo), "=f"(hi) : "l"(acc[i][jp]));
            v[2 * jp]     = __fadd_rn(lo, bias0[2 * jp]);
            v[2 * jp + 1] = __fadd_rn(hi, bias0[2 * jp + 1]);
        }
        float4* dst = (float4*)(g_xs + (size_t)row * 1024 + n0 + tn * 8);
        dst[0] = make_float4(v[0], v[1], v[2], v[3]);
        dst[1] = make_float4(v[4], v[5], v[6], v[7]);
    }
}

// ---------------- recurrence: HMMA + register weights + mbarrier cluster sync ----------
// 16 clusters of 8 CTAs; CTA rank r owns h-slice [32r,32r+32), computes its own gate rows.
// Per step: HMMA (exact bf16->f32, bitwise) -> local gates -> elementwise -> broadcast
// bf16 h_q to all ranks (double-buffered) -> fence + remote mbarrier arrives -> parity wait.
__global__ void __launch_bounds__(128) __cluster_dims__(8, 1, 1)
k_recur(float* __restrict__ out) {
    __shared__ uint32_t hs2[2][128][8];   // [buf][k2][b] bf16x2 h state
    __shared__ float gs[128][9];          // [g_local][b]
    __shared__ alignas(8) unsigned long long mbar;

    const int tid  = threadIdx.x;
    const int lane = tid & 31, warp = tid >> 5;
    const int gid  = lane >> 2, tig = lane & 3;
    const int rank  = blockIdx.x & 7;
    const int bbase = (blockIdx.x >> 3) * 4;

    for (int i = tid; i < 2 * 128 * 8; i += 128) ((uint32_t*)hs2)[i] = 0u;

    uint32_t mbar_sb;
    asm("{ .reg .u64 t0; cvta.to.shared.u64 t0, %1; cvt.u32.u64 %0, t0; }"
        : "=r"(mbar_sb) : "l"(&mbar));
    if (tid == 0)
        asm volatile("mbarrier.init.shared.b64 [%0], 8;" :: "r"(mbar_sb) : "memory");

    // A fragments (w_hh) -> registers, loaded once
    uint32_t afr[2][16][4];
    const uint32_t* W = (const uint32_t*)g_Whh;
    const int g0 = warp * 256 + rank * 32;
#pragma unroll
    for (int mt = 0; mt < 2; mt++)
#pragma unroll
        for (int kt = 0; kt < 16; kt++) {
            int r = g0 + mt * 16 + gid;
            int cc = kt * 8 + tig;
            afr[mt][kt][0] = W[r * 128 + cc];
            afr[mt][kt][1] = W[(r + 8) * 128 + cc];
            afr[mt][kt][2] = W[r * 128 + cc + 4];
            afr[mt][kt][3] = W[(r + 8) * 128 + cc + 4];
        }

    const int b_ew = warp, hl = lane;
    const int hu = rank * 32 + hl;

    // remote h-slot + mbarrier addresses
    uint32_t hloc;
    asm("{ .reg .u64 t0; cvta.to.shared.u64 t0, %1; cvt.u32.u64 %0, t0; }"
        : "=r"(hloc) : "l"(&hs2[0][hu >> 1][b_ew]));
    uint32_t haddr[8], mbaddr[8];
#pragma unroll
    for (int r = 0; r < 8; r++) {
        asm("mapa.shared::cluster.u32 %0, %1, %2;" : "=r"(haddr[r]) : "r"(hloc), "r"(r));
        asm("mapa.shared::cluster.u32 %0, %1, %2;" : "=r"(mbaddr[r]) : "r"(mbar_sb), "r"(r));
    }

    float c = 0.0f;

    __syncthreads();
    // one-time full barrier: covers hs2 zero-fill + mbarrier init across the cluster
    asm volatile("barrier.cluster.arrive.aligned;\n\tbarrier.cluster.wait.aligned;" ::: "memory");

    // preload xs for t=0
    const float* xb0 = g_xs + (size_t)(bbase + b_ew) * 1024 + hu;
    float x0 = xb0[0], x1 = xb0[256], x2 = xb0[512], x3 = xb0[768];

    int ph = 0;
    for (int t = 0; t < 1024; t++) {
        const int buf = t & 1;

        // HMMA: this CTA's 128 gate rows over k=256
        float c0[4] = {0.f, 0.f, 0.f, 0.f}, c1[4] = {0.f, 0.f, 0.f, 0.f};
#pragma unroll
        for (int kt = 0; kt < 16; kt++) {
            uint32_t bfr[2];
            bfr[0] = hs2[buf][kt * 8 + tig][gid];
            bfr[1] = hs2[buf][kt * 8 + tig + 4][gid];
            mma16816(c0, afr[0][kt], bfr);
            mma16816(c1, afr[1][kt], bfr);
        }
        if (tig < 2) {
            int rb = warp * 32 + gid;
            gs[rb][2 * tig]          = c0[0];
            gs[rb][2 * tig + 1]      = c0[1];
            gs[rb + 8][2 * tig]      = c0[2];
            gs[rb + 8][2 * tig + 1]  = c0[3];
            gs[rb + 16][2 * tig]     = c1[0];
            gs[rb + 16][2 * tig + 1] = c1[1];
            gs[rb + 24][2 * tig]     = c1[2];
            gs[rb + 24][2 * tig + 1] = c1[3];
        }
        __syncthreads();

        // elementwise LSTM cell (bitwise-matched lowering)
        float gi = __fadd_rn(gs[hl][b_ew],      x0);
        float gf = __fadd_rn(gs[32 + hl][b_ew], x1);
        float gg = __fadd_rn(gs[64 + hl][b_ew], x2);
        float go = __fadd_rn(gs[96 + hl][b_ew], x3);

        // prefetch xs for t+1 now (x0..x3 consumed; ~800cy to next use)
        {
            int tn1 = t + 1 < 1024 ? t + 1 : 1023;
            const float* xn = g_xs + ((size_t)(tn1 * 64 + bbase + b_ew)) * 1024 + hu;
            x0 = xn[0]; x1 = xn[256]; x2 = xn[512]; x3 = xn[768];
        }

        float vi = sigmoid_ref(gi);
        float vf = sigmoid_ref(gf);
        float vg = tanh_ref(gg);
        float vo = sigmoid_ref(go);
        float cq = fq(c);
        c = __fmaf_rn(vf, cq, __fmul_rn(vi, vg));
        float h1 = __fmul_rn(vo, tanh_ref(c));

        out[((size_t)(bbase + b_ew) * 1024 + t) * 256 + hu] = h1;
        if (t == 1023) {
            size_t o = (size_t)16777216 + (size_t)(bbase + b_ew) * 256 + hu;
            out[o] = h1;          // hT
            out[o + 16384] = c;   // cT
        }

        // broadcast quantized h (exact in bf16) into NEXT buffer of all 8 CTAs
        uint16_t hb = (uint16_t)__bfloat16_as_ushort(__float2bfloat16(fq(h1)));
        uint32_t other = __shfl_xor_sync(0xffffffffu, (uint32_t)hb, 1);
        if ((hl & 1) == 0) {
            uint32_t packed = (uint32_t)hb | (other << 16);
            uint32_t off = (uint32_t)((buf ^ 1) * 4096);
#pragma unroll
            for (int r = 0; r < 8; r++)
                asm volatile("st.shared::cluster.b32 [%0], %1;"
                             :: "r"(haddr[r] + off), "r"(packed) : "memory");
        }
        __syncthreads();

        // one arrive per rank from thread 0 (release; fence covers all CTA threads' stores)
        if (tid == 0) {
            asm volatile("fence.acq_rel.cluster;" ::: "memory");
#pragma unroll
            for (int r = 0; r < 8; r++)
                asm volatile("mbarrier.arrive.release.cluster.shared::cluster.b64 _, [%0];"
                             :: "r"(mbaddr[r]) : "memory");
        }

        // wait for all 8 ranks' arrivals (phase parity = t&1)
        {
            uint32_t done;
            asm volatile(
                "{\n\t.reg .pred p;\n\t"
                "mbarrier.try_wait.parity.acquire.cluster.shared::cta.b64 p, [%1], %2;\n\t"
                "selp.b32 %0, 1, 0, p;\n\t}"
                : "=r"(done) : "r"(mbar_sb), "r"((uint32_t)ph) : "memory");
            if (!done) {
                asm volatile(
                    "{\n\t.reg .pred P1;\n\t"
                    "WL_%=:\n\t"
                    "mbarrier.try_wait.parity.acquire.cluster.shared::cta.b64 P1, [%0], %1, 0x989680;\n\t"
                    "@P1 bra.uni WD_%=;\n\t"
                    "bra.uni WL_%=;\n\t"
                    "WD_%=:\n\t}"
                    :: "r"(mbar_sb), "r"((uint32_t)ph) : "memory");
            }
        }
        ph ^= 1;
    }
}

// ---------------- launch ----------------
extern "C" void kernel_launch(void* const* d_in, const int* in_sizes, int n_in,
                              void* d_out, int out_size) {
    const float* x   = (const float*)d_in[0];
    const float* wih = (const float*)d_in[1];
    const float* whh = (const float*)d_in[2];
    const float* bih = (const float*)d_in[3];
    const float* bhh = (const float*)d_in[4];
    float* out = (float*)d_out;

    k_prep_w<<<1024, 256>>>(wih, whh, bih, bhh);
    k_gemm_chain<<<dim3(8, 512), 256>>>(x);
    k_recur<<<128, 128>>>(out);
}

// round 13
// speedup vs baseline: 1.5312x; 1.5312x over previous
#include <cuda_runtime.h>
#include <cuda_bf16.h>
#include <cstdint>

// Problem dims (fixed): B=64, T=1024, I=H=256, G=4H=1024
// ---------------- device scratch (static; no runtime allocations) ----------------
__device__ float         g_Wq[1024 * 256];              // quantized w_ih (fp32, exact grid values)
__device__ __nv_bfloat16 g_Whh[1024 * 256];             // quantized w_hh (exact in bf16)
__device__ float         g_bias[1024];                  // fq(b_ih)+fq(b_hh)
__device__ float         g_xs[(size_t)65536 * 1024];    // [t*64+b][g] input projections (+bias)

// ---------------- helpers ----------------
__device__ __forceinline__ float fq(float x) {
    float q = __fmul_rn(rintf(__fmul_rn(x, 16.0f)), 0.0625f);
    return fminf(fmaxf(q, -8.0f), 7.9375f);
}

// XLA EmitTanh: Cephes rational, FMA-contracted Horner, clamp 7.99881172180175781.
__device__ __forceinline__ float tanh_ref(float x) {
    float ax = fabsf(x);
    float xc = fminf(fmaxf(x, -7.99881172180175781f), 7.99881172180175781f);
    float x2 = __fmul_rn(xc, xc);
    float p = -2.76076847742355e-16f;
    p = __fmaf_rn(x2, p, 2.00018790482477e-13f);
    p = __fmaf_rn(x2, p, -8.60467152213735e-11f);
    p = __fmaf_rn(x2, p, 5.12229709037114e-08f);
    p = __fmaf_rn(x2, p, 1.48572235717979e-05f);
    p = __fmaf_rn(x2, p, 6.37261928875436e-04f);
    p = __fmaf_rn(x2, p, 4.89352455891786e-03f);
    float num = __fmul_rn(xc, p);
    float den = 1.19825839466702e-06f;
    den = __fmaf_rn(x2, den, 1.18534705686654e-04f);
    den = __fmaf_rn(x2, den, 2.26843463243900e-03f);
    den = __fmaf_rn(x2, den, 4.89352518554385e-03f);
    float r = __fdiv_rn(num, den);
    return (ax < 0.0004f) ? x : r;
}

// Faithfully-rounded expf (Juffa); immune to --use_fast_math.
__device__ __forceinline__ float expf_acc(float a) {
    float f, r, j, s, t;
    int i, ia;
    j = __fmaf_rn(1.442695f, a, 12582912.f);
    j = __fadd_rn(j, -12582912.f);
    f = __fmaf_rn(j, -6.93145752e-1f, a);
    f = __fmaf_rn(j, -1.42860677e-6f, f);
    i = (int)j;
    r = 1.37805939e-3f;
    r = __fmaf_rn(r, f, 8.37312452e-3f);
    r = __fmaf_rn(r, f, 4.16695364e-2f);
    r = __fmaf_rn(r, f, 1.66664720e-1f);
    r = __fmaf_rn(r, f, 4.99999851e-1f);
    r = __fmaf_rn(r, f, 1.00000000e+0f);
    r = __fmaf_rn(r, f, 1.00000000e+0f);
    ia = (i > 0) ? 0 : 0x83000000;
    s = __int_as_float(0x7f000000 + ia);
    t = __int_as_float((i << 23) - ia);
    r = __fmul_rn(__fmul_rn(r, s), t);
    if (fabsf(a) >= 104.0f) r = __fmul_rn(s, s);
    return r;
}

// XLA LogisticExpander: logistic(x) = 1 / (1 + exp(-x)), IEEE division.
__device__ __forceinline__ float sigmoid_ref(float x) {
    float e = expf_acc(-x);
    return __fdiv_rn(1.0f, __fadd_rn(1.0f, e));
}

__device__ __forceinline__ void mma16816(float c[4], const uint32_t a[4], const uint32_t b[2]) {
    asm volatile(
        "mma.sync.aligned.m16n8k16.row.col.f32.bf16.bf16.f32 "
        "{%0,%1,%2,%3}, {%4,%5,%6,%7}, {%8,%9}, {%0,%1,%2,%3};\n"
        : "+f"(c[0]), "+f"(c[1]), "+f"(c[2]), "+f"(c[3])
        : "r"(a[0]), "r"(a[1]), "r"(a[2]), "r"(a[3]), "r"(b[0]), "r"(b[1]));
}

// ---------------- prep kernel ----------------
__global__ void k_prep_w(const float* __restrict__ wih, const float* __restrict__ whh,
                         const float* __restrict__ bih, const float* __restrict__ bhh) {
    int g = blockIdx.x;          // 0..1023
    int k = threadIdx.x;         // 0..255
    g_Wq[g * 256 + k] = fq(wih[g * 256 + k]);
    g_Whh[g * 256 + k] = __float2bfloat16(fq(whh[g * 256 + k]));   // exact (j/16, |j|<=128)
    if (k == 0) g_bias[g] = __fadd_rn(fq(bih[g]), fq(bhh[g]));
}

// ---------------- input projection: exact sequential-chain SGEMM ----------------
// Same FMA chain order per element (bitwise identical); loads vectorized to LDS.128.
__global__ void __launch_bounds__(256) k_gemm_chain(const float* __restrict__ x) {
    __shared__ float Xs[32][132];   // [k][m], plain
    __shared__ float Ws[32][132];   // [k][g], plain
    const int tid = threadIdx.x;
    const int m0 = blockIdx.y * 128, n0 = blockIdx.x * 128;
    const int tm = tid >> 4;
    const int tn = tid & 15;

    float bias0[8];
#pragma unroll
    for (int j = 0; j < 8; j++) bias0[j] = g_bias[n0 + tn * 8 + j];

    unsigned long long acc[8][4];
#pragma unroll
    for (int i = 0; i < 8; i++)
#pragma unroll
        for (int j = 0; j < 4; j++) acc[i][j] = 0ull;

    for (int kc = 0; kc < 256; kc += 32) {
        __syncthreads();
#pragma unroll
        for (int j = 0; j < 4; j++) {
            int f4 = tid + 256 * j;
            int mr = f4 >> 3;
            int kq = (f4 & 7) * 4;
            float4 xv = *(const float4*)(x + (size_t)(m0 + mr) * 256 + kc + kq);
            Xs[kq + 0][mr] = xv.x;
            Xs[kq + 1][mr] = xv.y;
            Xs[kq + 2][mr] = xv.z;
            Xs[kq + 3][mr] = xv.w;
            float4 wv = *(const float4*)(g_Wq + (size_t)(n0 + mr) * 256 + kc + kq);
            Ws[kq + 0][mr] = wv.x;
            Ws[kq + 1][mr] = wv.y;
            Ws[kq + 2][mr] = wv.z;
            Ws[kq + 3][mr] = wv.w;
        }
        __syncthreads();
#pragma unroll 4
        for (int k = 0; k < 32; k++) {
            float4 xa = *(const float4*)&Xs[k][tm * 8];
            float4 xb = *(const float4*)&Xs[k][tm * 8 + 4];
            float4 wa = *(const float4*)&Ws[k][tn * 8];
            float4 wb = *(const float4*)&Ws[k][tn * 8 + 4];
            unsigned long long a2[8];
            asm("mov.b64 %0, {%1, %1};" : "=l"(a2[0]) : "f"(xa.x));
            asm("mov.b64 %0, {%1, %1};" : "=l"(a2[1]) : "f"(xa.y));
            asm("mov.b64 %0, {%1, %1};" : "=l"(a2[2]) : "f"(xa.z));
            asm("mov.b64 %0, {%1, %1};" : "=l"(a2[3]) : "f"(xa.w));
            asm("mov.b64 %0, {%1, %1};" : "=l"(a2[4]) : "f"(xb.x));
            asm("mov.b64 %0, {%1, %1};" : "=l"(a2[5]) : "f"(xb.y));
            asm("mov.b64 %0, {%1, %1};" : "=l"(a2[6]) : "f"(xb.z));
            asm("mov.b64 %0, {%1, %1};" : "=l"(a2[7]) : "f"(xb.w));
            unsigned long long b2[4];
            asm("mov.b64 %0, {%1, %2};" : "=l"(b2[0]) : "f"(wa.x), "f"(wa.y));
            asm("mov.b64 %0, {%1, %2};" : "=l"(b2[1]) : "f"(wa.z), "f"(wa.w));
            asm("mov.b64 %0, {%1, %2};" : "=l"(b2[2]) : "f"(wb.x), "f"(wb.y));
            asm("mov.b64 %0, {%1, %2};" : "=l"(b2[3]) : "f"(wb.z), "f"(wb.w));
#pragma unroll
            for (int i = 0; i < 8; i++)
#pragma unroll
                for (int jp = 0; jp < 4; jp++)
                    asm("fma.rn.f32x2 %0, %1, %2, %0;" : "+l"(acc[i][jp]) : "l"(a2[i]), "l"(b2[jp]));
        }
    }

#pragma unroll
    for (int i = 0; i < 8; i++) {
        int m = m0 + tm * 8 + i;
        int row = (m & 1023) * 64 + (m >> 10);
        float v[8];
#pragma unroll
        for (int jp = 0; jp < 4; jp++) {
            float lo, hi;
            asm("mov.b64 {%0, %1}, %2;" : "=f"(lo), "=f"(hi) : "l"(acc[i][jp]));
            v[2 * jp]     = __fadd_rn(lo, bias0[2 * jp]);
            v[2 * jp + 1] = __fadd_rn(hi, bias0[2 * jp + 1]);
        }
        float4* dst = (float4*)(g_xs + (size_t)row * 1024 + n0 + tn * 8);
        dst[0] = make_float4(v[0], v[1], v[2], v[3]);
        dst[1] = make_float4(v[4], v[5], v[6], v[7]);
    }
}

// ---------------- recurrence: HMMA + register weights + split cluster barrier ----------
// R11 protocol (hardware barrier.cluster — measured faster than mbarrier fanout in R12),
// with arrive/wait split so the out-store + xs prefetch hide behind cluster skew.
__global__ void __launch_bounds__(128) __cluster_dims__(8, 1, 1)
k_recur(float* __restrict__ out) {
    __shared__ uint32_t hs2[2][128][8];   // [buf][k2][b] bf16x2 h state
    __shared__ float gs[128][9];          // [g_local][b]

    const int tid  = threadIdx.x;
    const int lane = tid & 31, warp = tid >> 5;
    const int gid  = lane >> 2, tig = lane & 3;
    const int rank  = blockIdx.x & 7;
    const int bbase = (blockIdx.x >> 3) * 4;

    for (int i = tid; i < 2 * 128 * 8; i += 128) ((uint32_t*)hs2)[i] = 0u;

    // A fragments (w_hh) -> registers, loaded once
    uint32_t afr[2][16][4];
    const uint32_t* W = (const uint32_t*)g_Whh;
    const int g0 = warp * 256 + rank * 32;
#pragma unroll
    for (int mt = 0; mt < 2; mt++)
#pragma unroll
        for (int kt = 0; kt < 16; kt++) {
            int r = g0 + mt * 16 + gid;
            int cc = kt * 8 + tig;
            afr[mt][kt][0] = W[r * 128 + cc];
            afr[mt][kt][1] = W[(r + 8) * 128 + cc];
            afr[mt][kt][2] = W[r * 128 + cc + 4];
            afr[mt][kt][3] = W[(r + 8) * 128 + cc + 4];
        }

    const int b_ew = warp, hl = lane;
    const int hu = rank * 32 + hl;

    // remote h-slot addresses (buffer 0; buffer stride = 4096 B)
    uint32_t hloc;
    asm("{ .reg .u64 t0; cvta.to.shared.u64 t0, %1; cvt.u32.u64 %0, t0; }"
        : "=r"(hloc) : "l"(&hs2[0][hu >> 1][b_ew]));
    uint32_t haddr[8];
#pragma unroll
    for (int r = 0; r < 8; r++)
        asm("mapa.shared::cluster.u32 %0, %1, %2;" : "=r"(haddr[r]) : "r"(hloc), "r"(r));

    float c = 0.0f;

    __syncthreads();
    asm volatile("barrier.cluster.arrive.aligned;\n\tbarrier.cluster.wait.aligned;" ::: "memory");

    // preload xs for t=0
    const float* xb0 = g_xs + (size_t)(bbase + b_ew) * 1024 + hu;
    float x0 = xb0[0], x1 = xb0[256], x2 = xb0[512], x3 = xb0[768];

    for (int t = 0; t < 1024; t++) {
        const int buf = t & 1;

        // HMMA: this CTA's 128 gate rows over k=256 (exact -> bitwise)
        float c0[4] = {0.f, 0.f, 0.f, 0.f}, c1[4] = {0.f, 0.f, 0.f, 0.f};
#pragma unroll
        for (int kt = 0; kt < 16; kt++) {
            uint32_t bfr[2];
            bfr[0] = hs2[buf][kt * 8 + tig][gid];
            bfr[1] = hs2[buf][kt * 8 + tig + 4][gid];
            mma16816(c0, afr[0][kt], bfr);
            mma16816(c1, afr[1][kt], bfr);
        }
        if (tig < 2) {
            int rb = warp * 32 + gid;
            gs[rb][2 * tig]          = c0[0];
            gs[rb][2 * tig + 1]      = c0[1];
            gs[rb + 8][2 * tig]      = c0[2];
            gs[rb + 8][2 * tig + 1]  = c0[3];
            gs[rb + 16][2 * tig]     = c1[0];
            gs[rb + 16][2 * tig + 1] = c1[1];
            gs[rb + 24][2 * tig]     = c1[2];
            gs[rb + 24][2 * tig + 1] = c1[3];
        }
        __syncthreads();

        // gate adds (bitwise-matched lowering)
        float gi = __fadd_rn(gs[hl][b_ew],      x0);
        float gf = __fadd_rn(gs[32 + hl][b_ew], x1);
        float gg = __fadd_rn(gs[64 + hl][b_ew], x2);
        float go = __fadd_rn(gs[96 + hl][b_ew], x3);

        // prefetch xs for t+1 (x0..x3 consumed; covered by transcendentals + barrier)
        {
            int tn1 = t + 1 < 1024 ? t + 1 : 1023;
            const float* xn = g_xs + ((size_t)(tn1 * 64 + bbase + b_ew)) * 1024 + hu;
            x0 = xn[0]; x1 = xn[256]; x2 = xn[512]; x3 = xn[768];
        }

        float vi = sigmoid_ref(gi);
        float vf = sigmoid_ref(gf);
        float vg = tanh_ref(gg);
        float vo = sigmoid_ref(go);
        float cq = fq(c);
        c = __fmaf_rn(vf, cq, __fmul_rn(vi, vg));
        float h1 = __fmul_rn(vo, tanh_ref(c));

        // broadcast quantized h (exact in bf16) into NEXT buffer of all 8 CTAs
        uint16_t hb = (uint16_t)__bfloat16_as_ushort(__float2bfloat16(fq(h1)));
        uint32_t other = __shfl_xor_sync(0xffffffffu, (uint32_t)hb, 1);
        if ((hl & 1) == 0) {
            uint32_t packed = (uint32_t)hb | (other << 16);
            uint32_t off = (uint32_t)((buf ^ 1) * 4096);
#pragma unroll
            for (int r = 0; r < 8; r++)
                asm volatile("st.shared::cluster.b32 [%0], %1;"
                             :: "r"(haddr[r] + off), "r"(packed) : "memory");
        }

        // arrive (release) -> overlap out-store with cluster skew -> wait (acquire)
        asm volatile("barrier.cluster.arrive.aligned;" ::: "memory");

        out[((size_t)(bbase + b_ew) * 1024 + t) * 256 + hu] = h1;
        if (t == 1023) {
            size_t o = (size_t)16777216 + (size_t)(bbase + b_ew) * 256 + hu;
            out[o] = h1;          // hT
            out[o + 16384] = c;   // cT
        }

        asm volatile("barrier.cluster.wait.aligned;" ::: "memory");
    }
}

// ---------------- launch ----------------
extern "C" void kernel_launch(void* const* d_in, const int* in_sizes, int n_in,
                              void* d_out, int out_size) {
    const float* x   = (const float*)d_in[0];
    const float* wih = (const float*)d_in[1];
    const float* whh = (const float*)d_in[2];
    const float* bih = (const float*)d_in[3];
    const float* bhh = (const float*)d_in[4];
    float* out = (float*)d_out;

    k_prep_w<<<1024, 256>>>(wih, whh, bih, bhh);
    k_gemm_chain<<<dim3(8, 512), 256>>>(x);
    k_recur<<<128, 128>>>(out);
}

// round 14
// speedup vs baseline: 1.7766x; 1.1602x over previous
#include <cuda_runtime.h>
#include <cuda_bf16.h>
#include <cstdint>

// Problem dims (fixed): B=64, T=1024, I=H=256, G=4H=1024
// ---------------- device scratch (static; no runtime allocations) ----------------
__device__ float         g_Wq[1024 * 256];              // quantized w_ih (fp32, exact grid values)
__device__ __nv_bfloat16 g_Whh[1024 * 256];             // quantized w_hh (exact in bf16)
__device__ float         g_bias[1024];                  // fq(b_ih)+fq(b_hh)
__device__ float         g_xs[(size_t)65536 * 1024];    // [t*64+b][g] input projections (+bias)

// ---------------- helpers ----------------
__device__ __forceinline__ float fq(float x) {
    float q = __fmul_rn(rintf(__fmul_rn(x, 16.0f)), 0.0625f);
    return fminf(fmaxf(q, -8.0f), 7.9375f);
}

// XLA EmitTanh: Cephes rational, FMA-contracted Horner, clamp 7.99881172180175781.
__device__ __forceinline__ float tanh_ref(float x) {
    float ax = fabsf(x);
    float xc = fminf(fmaxf(x, -7.99881172180175781f), 7.99881172180175781f);
    float x2 = __fmul_rn(xc, xc);
    float p = -2.76076847742355e-16f;
    p = __fmaf_rn(x2, p, 2.00018790482477e-13f);
    p = __fmaf_rn(x2, p, -8.60467152213735e-11f);
    p = __fmaf_rn(x2, p, 5.12229709037114e-08f);
    p = __fmaf_rn(x2, p, 1.48572235717979e-05f);
    p = __fmaf_rn(x2, p, 6.37261928875436e-04f);
    p = __fmaf_rn(x2, p, 4.89352455891786e-03f);
    float num = __fmul_rn(xc, p);
    float den = 1.19825839466702e-06f;
    den = __fmaf_rn(x2, den, 1.18534705686654e-04f);
    den = __fmaf_rn(x2, den, 2.26843463243900e-03f);
    den = __fmaf_rn(x2, den, 4.89352518554385e-03f);
    float r = __fdiv_rn(num, den);
    return (ax < 0.0004f) ? x : r;
}

// Faithfully-rounded expf (Juffa); immune to --use_fast_math.
__device__ __forceinline__ float expf_acc(float a) {
    float f, r, j, s, t;
    int i, ia;
    j = __fmaf_rn(1.442695f, a, 12582912.f);
    j = __fadd_rn(j, -12582912.f);
    f = __fmaf_rn(j, -6.93145752e-1f, a);
    f = __fmaf_rn(j, -1.42860677e-6f, f);
    i = (int)j;
    r = 1.37805939e-3f;
    r = __fmaf_rn(r, f, 8.37312452e-3f);
    r = __fmaf_rn(r, f, 4.16695364e-2f);
    r = __fmaf_rn(r, f, 1.66664720e-1f);
    r = __fmaf_rn(r, f, 4.99999851e-1f);
    r = __fmaf_rn(r, f, 1.00000000e+0f);
    r = __fmaf_rn(r, f, 1.00000000e+0f);
    ia = (i > 0) ? 0 : 0x83000000;
    s = __int_as_float(0x7f000000 + ia);
    t = __int_as_float((i << 23) - ia);
    r = __fmul_rn(__fmul_rn(r, s), t);
    if (fabsf(a) >= 104.0f) r = __fmul_rn(s, s);
    return r;
}

// XLA LogisticExpander: logistic(x) = 1 / (1 + exp(-x)), IEEE division.
__device__ __forceinline__ float sigmoid_ref(float x) {
    float e = expf_acc(-x);
    return __fdiv_rn(1.0f, __fadd_rn(1.0f, e));
}

__device__ __forceinline__ void mma16816(float c[4], const uint32_t a[4], const uint32_t b[2]) {
    asm volatile(
        "mma.sync.aligned.m16n8k16.row.col.f32.bf16.bf16.f32 "
        "{%0,%1,%2,%3}, {%4,%5,%6,%7}, {%8,%9}, {%0,%1,%2,%3};\n"
        : "+f"(c[0]), "+f"(c[1]), "+f"(c[2]), "+f"(c[3])
        : "r"(a[0]), "r"(a[1]), "r"(a[2]), "r"(a[3]), "r"(b[0]), "r"(b[1]));
}

// ---------------- prep kernel ----------------
__global__ void k_prep_w(const float* __restrict__ wih, const float* __restrict__ whh,
                         const float* __restrict__ bih, const float* __restrict__ bhh) {
    int g = blockIdx.x;          // 0..1023
    int k = threadIdx.x;         // 0..255
    g_Wq[g * 256 + k] = fq(wih[g * 256 + k]);
    g_Whh[g * 256 + k] = __float2bfloat16(fq(whh[g * 256 + k]));   // exact (j/16, |j|<=128)
    if (k == 0) g_bias[g] = __fadd_rn(fq(bih[g]), fq(bhh[g]));
}

// ---------------- input projection: exact sequential-chain SGEMM ----------------
// Same FMA chain order per element (bitwise identical); loads vectorized to LDS.128.
__global__ void __launch_bounds__(256) k_gemm_chain(const float* __restrict__ x) {
    __shared__ float Xs[32][132];   // [k][m], plain
    __shared__ float Ws[32][132];   // [k][g], plain
    const int tid = threadIdx.x;
    const int m0 = blockIdx.y * 128, n0 = blockIdx.x * 128;
    const int tm = tid >> 4;
    const int tn = tid & 15;

    float bias0[8];
#pragma unroll
    for (int j = 0; j < 8; j++) bias0[j] = g_bias[n0 + tn * 8 + j];

    unsigned long long acc[8][4];
#pragma unroll
    for (int i = 0; i < 8; i++)
#pragma unroll
        for (int j = 0; j < 4; j++) acc[i][j] = 0ull;

    for (int kc = 0; kc < 256; kc += 32) {
        __syncthreads();
#pragma unroll
        for (int j = 0; j < 4; j++) {
            int f4 = tid + 256 * j;
            int mr = f4 >> 3;
            int kq = (f4 & 7) * 4;
            float4 xv = *(const float4*)(x + (size_t)(m0 + mr) * 256 + kc + kq);
            Xs[kq + 0][mr] = xv.x;
            Xs[kq + 1][mr] = xv.y;
            Xs[kq + 2][mr] = xv.z;
            Xs[kq + 3][mr] = xv.w;
            float4 wv = *(const float4*)(g_Wq + (size_t)(n0 + mr) * 256 + kc + kq);
            Ws[kq + 0][mr] = wv.x;
            Ws[kq + 1][mr] = wv.y;
            Ws[kq + 2][mr] = wv.z;
            Ws[kq + 3][mr] = wv.w;
        }
        __syncthreads();
#pragma unroll 4
        for (int k = 0; k < 32; k++) {
            float4 xa = *(const float4*)&Xs[k][tm * 8];
            float4 xb = *(const float4*)&Xs[k][tm * 8 + 4];
            float4 wa = *(const float4*)&Ws[k][tn * 8];
            float4 wb = *(const float4*)&Ws[k][tn * 8 + 4];
            unsigned long long a2[8];
            asm("mov.b64 %0, {%1, %1};" : "=l"(a2[0]) : "f"(xa.x));
            asm("mov.b64 %0, {%1, %1};" : "=l"(a2[1]) : "f"(xa.y));
            asm("mov.b64 %0, {%1, %1};" : "=l"(a2[2]) : "f"(xa.z));
            asm("mov.b64 %0, {%1, %1};" : "=l"(a2[3]) : "f"(xa.w));
            asm("mov.b64 %0, {%1, %1};" : "=l"(a2[4]) : "f"(xb.x));
            asm("mov.b64 %0, {%1, %1};" : "=l"(a2[5]) : "f"(xb.y));
            asm("mov.b64 %0, {%1, %1};" : "=l"(a2[6]) : "f"(xb.z));
            asm("mov.b64 %0, {%1, %1};" : "=l"(a2[7]) : "f"(xb.w));
            unsigned long long b2[4];
            asm("mov.b64 %0, {%1, %2};" : "=l"(b2[0]) : "f"(wa.x), "f"(wa.y));
            asm("mov.b64 %0, {%1, %2};" : "=l"(b2[1]) : "f"(wa.z), "f"(wa.w));
            asm("mov.b64 %0, {%1, %2};" : "=l"(b2[2]) : "f"(wb.x), "f"(wb.y));
            asm("mov.b64 %0, {%1, %2};" : "=l"(b2[3]) : "f"(wb.z), "f"(wb.w));
#pragma unroll
            for (int i = 0; i < 8; i++)
#pragma unroll
                for (int jp = 0; jp < 4; jp++)
                    asm("fma.rn.f32x2 %0, %1, %2, %0;" : "+l"(acc[i][jp]) : "l"(a2[i]), "l"(b2[jp]));
        }
    }

#pragma unroll
    for (int i = 0; i < 8; i++) {
        int m = m0 + tm * 8 + i;
        int row = (m & 1023) * 64 + (m >> 10);
        float v[8];
#pragma unroll
        for (int jp = 0; jp < 4; jp++) {
            float lo, hi;
            asm("mov.b64 {%0, %1}, %2;" : "=f"(lo), "=f"(hi) : "l"(acc[i][jp]));
            v[2 * jp]     = __fadd_rn(lo, bias0[2 * jp]);
            v[2 * jp + 1] = __fadd_rn(hi, bias0[2 * jp + 1]);
        }
        float4* dst = (float4*)(g_xs + (size_t)row * 1024 + n0 + tn * 8);
        dst[0] = make_float4(v[0], v[1], v[2], v[3]);
        dst[1] = make_float4(v[4], v[5], v[6], v[7]);
    }
}

// ---------------- recurrence: 4-CTA clusters x 256 threads ----------------
// 16 batch-groups x 4 CTAs. CTA rank r owns h-units [64r, 64r+64) and computes its
// 256 gate rows (8 warps x 32 rows, weights register-resident). 2 warps/SMSP hide
// MMA-chain + div stalls. Broadcast fanout = 4. Arithmetic identical -> bitwise.
__global__ void __launch_bounds__(256) __cluster_dims__(4, 1, 1)
k_recur(float* __restrict__ out) {
    __shared__ uint32_t hs2[2][128][8];   // [buf][k2][b] bf16x2 h state (cols 4..7 stay 0)
    __shared__ float gs[256][9];          // [gate*64 + local_unit][b]

    const int tid  = threadIdx.x;
    const int lane = tid & 31, warp = tid >> 5;
    const int gid  = lane >> 2, tig = lane & 3;
    const int rank  = blockIdx.x & 3;
    const int bbase = (blockIdx.x >> 2) * 4;

    for (int i = tid; i < 2 * 128 * 8; i += 256) ((uint32_t*)hs2)[i] = 0u;

    // A fragments (w_hh) -> registers, loaded once. This warp's 32 gate rows.
    uint32_t afr[2][16][4];
    const uint32_t* W = (const uint32_t*)g_Whh;
    const int g0 = (warp >> 1) * 256 + rank * 64 + (warp & 1) * 32;
#pragma unroll
    for (int mt = 0; mt < 2; mt++)
#pragma unroll
        for (int kt = 0; kt < 16; kt++) {
            int r = g0 + mt * 16 + gid;
            int cc = kt * 8 + tig;
            afr[mt][kt][0] = W[r * 128 + cc];
            afr[mt][kt][1] = W[(r + 8) * 128 + cc];
            afr[mt][kt][2] = W[r * 128 + cc + 4];
            afr[mt][kt][3] = W[(r + 8) * 128 + cc + 4];
        }

    // elementwise identity: thread = (batch b_ew, local unit lu)
    const int b_ew = tid >> 6, lu = tid & 63;
    const int hu = rank * 64 + lu;

    // remote h-slot addresses (buffer 0; buffer stride = 4096 B)
    uint32_t hloc;
    asm("{ .reg .u64 t0; cvta.to.shared.u64 t0, %1; cvt.u32.u64 %0, t0; }"
        : "=r"(hloc) : "l"(&hs2[0][hu >> 1][b_ew]));
    uint32_t haddr[4];
#pragma unroll
    for (int r = 0; r < 4; r++)
        asm("mapa.shared::cluster.u32 %0, %1, %2;" : "=r"(haddr[r]) : "r"(hloc), "r"(r));

    float c = 0.0f;

    __syncthreads();
    asm volatile("barrier.cluster.arrive.aligned;\n\tbarrier.cluster.wait.aligned;" ::: "memory");

    // preload xs for t=0
    const float* xb0 = g_xs + (size_t)(bbase + b_ew) * 1024 + hu;
    float x0 = xb0[0], x1 = xb0[256], x2 = xb0[512], x3 = xb0[768];

    for (int t = 0; t < 1024; t++) {
        const int buf = t & 1;

        // HMMA: this warp's 32 gate rows over k=256 (exact -> bitwise)
        float c0[4] = {0.f, 0.f, 0.f, 0.f}, c1[4] = {0.f, 0.f, 0.f, 0.f};
#pragma unroll
        for (int kt = 0; kt < 16; kt++) {
            uint32_t bfr[2];
            bfr[0] = hs2[buf][kt * 8 + tig][gid];
            bfr[1] = hs2[buf][kt * 8 + tig + 4][gid];
            mma16816(c0, afr[0][kt], bfr);
            mma16816(c1, afr[1][kt], bfr);
        }
        if (tig < 2) {
            int rb = (warp >> 1) * 64 + (warp & 1) * 32 + gid;
            gs[rb][2 * tig]          = c0[0];
            gs[rb][2 * tig + 1]      = c0[1];
            gs[rb + 8][2 * tig]      = c0[2];
            gs[rb + 8][2 * tig + 1]  = c0[3];
            gs[rb + 16][2 * tig]     = c1[0];
            gs[rb + 16][2 * tig + 1] = c1[1];
            gs[rb + 24][2 * tig]     = c1[2];
            gs[rb + 24][2 * tig + 1] = c1[3];
        }
        __syncthreads();

        // gate adds (bitwise-matched lowering)
        float gi = __fadd_rn(gs[lu][b_ew],       x0);
        float gf = __fadd_rn(gs[64 + lu][b_ew],  x1);
        float gg = __fadd_rn(gs[128 + lu][b_ew], x2);
        float go = __fadd_rn(gs[192 + lu][b_ew], x3);

        // prefetch xs for t+1 (covered by transcendentals + barrier)
        {
            int tn1 = t + 1 < 1024 ? t + 1 : 1023;
            const float* xn = g_xs + ((size_t)(tn1 * 64 + bbase + b_ew)) * 1024 + hu;
            x0 = xn[0]; x1 = xn[256]; x2 = xn[512]; x3 = xn[768];
        }

        float vi = sigmoid_ref(gi);
        float vf = sigmoid_ref(gf);
        float vg = tanh_ref(gg);
        float vo = sigmoid_ref(go);
        float cq = fq(c);
        c = __fmaf_rn(vf, cq, __fmul_rn(vi, vg));
        float h1 = __fmul_rn(vo, tanh_ref(c));

        // broadcast quantized h (exact in bf16) into NEXT buffer of all 4 CTAs
        uint16_t hb = (uint16_t)__bfloat16_as_ushort(__float2bfloat16(fq(h1)));
        uint32_t other = __shfl_xor_sync(0xffffffffu, (uint32_t)hb, 1);
        if ((lane & 1) == 0) {
            uint32_t packed = (uint32_t)hb | (other << 16);
            uint32_t off = (uint32_t)((buf ^ 1) * 4096);
#pragma unroll
            for (int r = 0; r < 4; r++)
                asm volatile("st.shared::cluster.b32 [%0], %1;"
                             :: "r"(haddr[r] + off), "r"(packed) : "memory");
        }

        // arrive (release) -> overlap out-store with cluster skew -> wait (acquire)
        asm volatile("barrier.cluster.arrive.aligned;" ::: "memory");

        out[((size_t)(bbase + b_ew) * 1024 + t) * 256 + hu] = h1;
        if (t == 1023) {
            size_t o = (size_t)16777216 + (size_t)(bbase + b_ew) * 256 + hu;
            out[o] = h1;          // hT
            out[o + 16384] = c;   // cT
        }

        asm volatile("barrier.cluster.wait.aligned;" ::: "memory");
    }
}

// ---------------- launch ----------------
extern "C" void kernel_launch(void* const* d_in, const int* in_sizes, int n_in,
                              void* d_out, int out_size) {
    const float* x   = (const float*)d_in[0];
    const float* wih = (const float*)d_in[1];
    const float* whh = (const float*)d_in[2];
    const float* bih = (const float*)d_in[3];
    const float* bhh = (const float*)d_in[4];
    float* out = (float*)d_out;

    k_prep_w<<<1024, 256>>>(wih, whh, bih, bhh);
    k_gemm_chain<<<dim3(8, 512), 256>>>(x);
    k_recur<<<64, 256>>>(out);
}